// round 2
// baseline (speedup 1.0000x reference)
#include <cuda_runtime.h>

#define NPIX 22500
#define NB 32
#define NCHUNK 6
#define CHUNK 3750   // 22500 / 6
#define TPB 256
#define HB 64
#define LOB (-3.0f)
#define STEP (6.0f / 63.0f)
#define INV_SIG2 2500.0f   // 1 / 0.02^2

// Scratch (no allocations allowed): prep data + per-chunk partial histograms
__device__ float g_prep[3 * NB * NPIX];                    // d01, d02, Iy planes
__device__ float g_part[NB * 3 * NCHUNK * HB * HB];        // partial hists

__device__ __forceinline__ float kq(float d) {
    // inverse-quadratic soft-bin kernel: 1 / (1 + d^2 / sigma^2)
    float q = fmaf(d * d, INV_SIG2, 1.0f);
    float r;
    asm("rcp.approx.f32 %0, %1;" : "=f"(r) : "f"(q));
    return r;
}

// ---------------------------------------------------------------------------
// Kernel 1: per-pixel prep — clip, logs, intensity
// ---------------------------------------------------------------------------
__global__ void __launch_bounds__(TPB) prep_kernel(const float* __restrict__ x) {
    int idx = blockIdx.x * blockDim.x + threadIdx.x;
    if (idx >= NB * NPIX) return;
    int b = idx / NPIX;
    int p = idx - b * NPIX;
    const float* xb = x + (size_t)b * 3 * NPIX;
    float r  = fminf(fmaxf(xb[p],            0.0f), 1.0f);
    float g  = fminf(fmaxf(xb[NPIX + p],     0.0f), 1.0f);
    float bl = fminf(fmaxf(xb[2 * NPIX + p], 0.0f), 1.0f);
    float iy = sqrtf(fmaf(r, r, fmaf(g, g, fmaf(bl, bl, 1e-6f))));
    float l0 = logf(r  + 1e-6f);
    float l1 = logf(g  + 1e-6f);
    float l2 = logf(bl + 1e-6f);
    g_prep[idx]                 = l0 - l1;   // d01
    g_prep[NB * NPIX + idx]     = l0 - l2;   // d02
    g_prep[2 * NB * NPIX + idx] = iy;
}

// ---------------------------------------------------------------------------
// Kernel 2: main — per (b, c, chunk) CTA, 32-pixel tiles, f32x2 outer product
// ---------------------------------------------------------------------------
__global__ void __launch_bounds__(TPB, 4) hist_kernel() {
    __shared__ float sKu[32][64];   // Iy * Ku  (weight folded in)
    __shared__ float sKv[32][64];

    int cta   = blockIdx.x;           // 0 .. 96*NCHUNK-1
    int chunk = cta % NCHUNK;
    int bc    = cta / NCHUNK;
    int b     = bc / 3;
    int c     = bc - b * 3;

    int t   = threadIdx.x;
    int tu  = t >> 4;                 // 0..15 -> u-tile
    int tv  = t & 15;                 // 0..15 -> v-tile
    int pix = t >> 3;                 // 0..31  (8 threads per pixel in gen phase)
    int lane8 = t & 7;
    int boff  = lane8 * 16;           // 0..112: which 16 of the 128 kernel values
    bool isKu = (boff < 64);
    int  bin0 = boff & 63;            // logical bin index within the Ku/Kv table
    float* dst = isKu ? &sKu[pix][bin0] : &sKv[pix][bin0];

    unsigned long long acc[4][2];
    #pragma unroll
    for (int i = 0; i < 4; ++i) { acc[i][0] = 0ull; acc[i][1] = 0ull; }

    const float* pd01 = g_prep + (size_t)b * NPIX;
    const float* pd02 = pd01 + (size_t)NB * NPIX;
    const float* piy  = pd01 + (size_t)2 * NB * NPIX;
    int p0 = chunk * CHUNK;

    const int NTILES = (CHUNK + 31) / 32;   // 118 (last tile partial)
    for (int tile = 0; tile < NTILES; ++tile) {
        int p = p0 + tile * 32 + pix;
        float d01 = 0.0f, d02 = 0.0f, iy = 0.0f;
        if (p < p0 + CHUNK) {
            d01 = pd01[p];
            d02 = pd02[p];
            iy  = piy[p];    // OOB pixels keep iy=0 -> Ku row = 0 -> no contribution
        }
        float U, V;
        if (c == 0)      { U =  d01; V =  d02; }
        else if (c == 1) { U = -d01; V =  d02 - d01; }
        else             { U = -d02; V =  d01 - d02; }

        float val   = isKu ? U  : V;
        float scale = isKu ? iy : 1.0f;
        float dBase = val - (LOB + (float)bin0 * STEP);

        #pragma unroll
        for (int q = 0; q < 4; ++q) {
            float4 o;
            o.x = kq(dBase - (float)(4 * q + 0) * STEP) * scale;
            o.y = kq(dBase - (float)(4 * q + 1) * STEP) * scale;
            o.z = kq(dBase - (float)(4 * q + 2) * STEP) * scale;
            o.w = kq(dBase - (float)(4 * q + 3) * STEP) * scale;
            *reinterpret_cast<float4*>(dst + 4 * q) = o;
        }
        __syncthreads();

        const float* kuP = &sKu[0][tu * 4];
        const float* kvP = &sKv[0][tv * 4];
        #pragma unroll 8
        for (int pl = 0; pl < 32; ++pl) {
            float4 a4 = *reinterpret_cast<const float4*>(kuP + pl * 64);
            float4 k4 = *reinterpret_cast<const float4*>(kvP + pl * 64);
            unsigned long long kv01, kv23;
            asm("mov.b64 %0, {%1, %2};" : "=l"(kv01)
                : "r"(__float_as_uint(k4.x)), "r"(__float_as_uint(k4.y)));
            asm("mov.b64 %0, {%1, %2};" : "=l"(kv23)
                : "r"(__float_as_uint(k4.z)), "r"(__float_as_uint(k4.w)));
            float av[4] = {a4.x, a4.y, a4.z, a4.w};
            #pragma unroll
            for (int i = 0; i < 4; ++i) {
                unsigned long long a2;
                asm("mov.b64 %0, {%1, %1};" : "=l"(a2) : "r"(__float_as_uint(av[i])));
                asm("fma.rn.f32x2 %0, %1, %2, %0;" : "+l"(acc[i][0]) : "l"(a2), "l"(kv01));
                asm("fma.rn.f32x2 %0, %1, %2, %0;" : "+l"(acc[i][1]) : "l"(a2), "l"(kv23));
            }
        }
        __syncthreads();
    }

    // write this CTA's 64x64 partial (deterministic, no atomics)
    float* base = g_part + (size_t)cta * (HB * HB);
    #pragma unroll
    for (int i = 0; i < 4; ++i) {
        int u = tu * 4 + i;
        #pragma unroll
        for (int jp = 0; jp < 2; ++jp) {
            int v = tv * 4 + jp * 2;
            *reinterpret_cast<unsigned long long*>(base + u * HB + v) = acc[i][jp];
        }
    }
}

// ---------------------------------------------------------------------------
// Kernel 3: reduce chunk partials, per-batch normalize, write output
// ---------------------------------------------------------------------------
__global__ void __launch_bounds__(TPB) finalize_kernel(float* __restrict__ out) {
    int b = blockIdx.x;
    int t = threadIdx.x;
    float vals[48];
    float local = 0.0f;
    #pragma unroll
    for (int j = 0; j < 48; ++j) {
        int vi = t + TPB * j;            // 0 .. 12287 = c*4096 + u*64 + v
        int c  = vi >> 12;
        int uv = vi & 4095;
        const float* part = g_part + (size_t)(b * 3 + c) * NCHUNK * 4096 + uv;
        float s = 0.0f;
        #pragma unroll
        for (int k = 0; k < NCHUNK; ++k) s += part[k * 4096];
        vals[j] = s;
        local  += s;
    }
    __shared__ float red[TPB];
    red[t] = local;
    __syncthreads();
    #pragma unroll
    for (int s = TPB / 2; s > 0; s >>= 1) {
        if (t < s) red[t] += red[t + s];
        __syncthreads();
    }
    float inv = 1.0f / (red[0] + 1e-6f);
    #pragma unroll
    for (int j = 0; j < 48; ++j) {
        out[(size_t)b * 12288 + t + TPB * j] = vals[j] * inv;
    }
}

// ---------------------------------------------------------------------------
extern "C" void kernel_launch(void* const* d_in, const int* in_sizes, int n_in,
                              void* d_out, int out_size) {
    const float* x = (const float*)d_in[0];
    float* out = (float*)d_out;
    prep_kernel<<<(NB * NPIX + TPB - 1) / TPB, TPB>>>(x);
    hist_kernel<<<NB * 3 * NCHUNK, TPB>>>();
    finalize_kernel<<<NB, TPB>>>(out);
}